// round 14
// baseline (speedup 1.0000x reference)
#include <cuda_runtime.h>
#include <cuda_fp16.h>
#include <math.h>
#include <stdint.h>

#define BATCH 16
#define MAXPIX (268u * 268u)

// activations NHWC fp16 (single precision-term), ping-pong
__device__ __half g_actA[16u * MAXPIX * 64u];
__device__ __half g_actB[16u * MAXPIX * 64u];
// fp16 body weights, K-MAJOR: [5][16][tap 9][ic 64][oc 64]
__device__ __half g_wt[5u * 16u * 9u * 64u * 64u];
// fp16 tail weights: [16][tap 9][ic 64][oc 8(pad)]
__device__ __half g_twt[16u * 9u * 64u * 8u];

// ---------------- helpers ----------------
__device__ __forceinline__ uint32_t smem_u32(const void* p) {
    uint32_t a;
    asm("{ .reg .u64 t; cvta.to.shared.u64 t, %1; cvt.u32.u64 %0, t; }" : "=r"(a) : "l"(p));
    return a;
}
__device__ __forceinline__ uint32_t swz(uint32_t o)   { return o ^ ((o >> 3) & 0x70); }  // 128B rows
__device__ __forceinline__ uint32_t swz64(uint32_t o) { return o ^ ((o >> 3) & 0x30); }  // 64B rows

__device__ __forceinline__ void ldsm4(uint32_t r[4], uint32_t addr) {
    asm volatile("ldmatrix.sync.aligned.m8n8.x4.shared.b16 {%0,%1,%2,%3}, [%4];"
        : "=r"(r[0]), "=r"(r[1]), "=r"(r[2]), "=r"(r[3]) : "r"(addr));
}
__device__ __forceinline__ void ldsm4t(uint32_t r[4], uint32_t addr) {
    asm volatile("ldmatrix.sync.aligned.m8n8.x4.trans.shared.b16 {%0,%1,%2,%3}, [%4];"
        : "=r"(r[0]), "=r"(r[1]), "=r"(r[2]), "=r"(r[3]) : "r"(addr));
}
__device__ __forceinline__ void mma16816(float d[4], const uint32_t a[4], uint32_t b0, uint32_t b1) {
    asm volatile("mma.sync.aligned.m16n8k16.row.col.f32.f16.f16.f32 "
        "{%0,%1,%2,%3}, {%4,%5,%6,%7}, {%8,%9}, {%0,%1,%2,%3};"
        : "+f"(d[0]), "+f"(d[1]), "+f"(d[2]), "+f"(d[3])
        : "r"(a[0]), "r"(a[1]), "r"(a[2]), "r"(a[3]), "r"(b0), "r"(b1));
}
__device__ __forceinline__ void cp16(uint32_t dst, const void* src) {
    asm volatile("cp.async.cg.shared.global [%0], [%1], 16;" :: "r"(dst), "l"(src) : "memory");
}
#define CP_COMMIT() asm volatile("cp.async.commit_group;" ::: "memory")
#define CP_WAIT(n)  asm volatile("cp.async.wait_group %0;" :: "n"(n) : "memory")

// smem layout for body kernel (N-split CTA: 36KB weights + 2 x 23552 slabs)
#define SM_WS   0          // 9 x 4096 = 36864
#define SM_A0   36864
#define SM_A1   60416
#define SMEM_BODY 83968

// smem layout for tail kernel (8x16 px tile, 10x18 slab)
#define TSM_WS  0          // 9 x 1024 = 9216
#define TSM_A0  9216
#define TSM_A1  32768
#define SMEM_TAIL 56320

#define NTHR 256

// ---------------- weight prep: [l][b][tap][ic][oc], cw folded, fp16 ----------
__global__ void prep_kernel(const float* __restrict__ bw, float cw) {
    int idx = blockIdx.x * blockDim.x + threadIdx.x;
    const int N = 5 * 16 * 9 * 64 * 64;
    if (idx >= N) return;
    int oc = idx & 63;
    int ic = (idx >> 6) & 63;
    int tap = (idx >> 12) % 9;
    int rest = idx / (9 * 64 * 64);   // l*16+b
    float v = bw[(((size_t)rest * 64 + oc) * 64 + ic) * 9 + tap] * cw;
    g_wt[idx] = __float2half_rn(v);
}

// tail weights: [b][tap][ic][oc8], cw folded, oc>=3 zero
__global__ void prep_tail_kernel(const float* __restrict__ tw, float cw) {
    int idx = blockIdx.x * blockDim.x + threadIdx.x;
    const int N = 16 * 9 * 64 * 8;
    if (idx >= N) return;
    int oc = idx & 7;
    int ic = (idx >> 3) & 63;
    int tap = (idx >> 9) % 9;
    int b = idx / (9 * 64 * 8);
    float v = 0.f;
    if (oc < 3) v = tw[(((size_t)b * 3 + oc) * 64 + ic) * 9 + tap] * cw;
    g_twt[idx] = __float2half_rn(v);
}

// ---------------- head (scalar fp32, writes NHWC fp16) ----------------
__global__ __launch_bounds__(256)
void head_kernel(const float* __restrict__ noise, const float* __restrict__ hw,
                 const float* __restrict__ hb, __half* __restrict__ oh,
                 float cw, float cb)
{
    const int Sout = 268;
    int b = blockIdx.z >> 2;
    int oc0 = (blockIdx.z & 3) << 4;
    int tx0 = blockIdx.x * 32, ty0 = blockIdx.y * 8;
    int tid = threadIdx.x, tx = tid & 31, ty = tid >> 5;

    __shared__ __align__(16) float ws[3 * 9 * 16];
    __shared__ float xs[3 * 10 * 34];

    for (int i = tid; i < 3 * 144; i += 256) {
        int oc = i & 15, k = (i >> 4) % 9, ic = i / 144;
        ws[i] = hw[((b * 64 + oc0 + oc) * 3 + ic) * 9 + k];
    }
    for (int i = tid; i < 3 * 340; i += 256) {
        int ic = i / 340, rem = i % 340, r = rem / 34, c = rem % 34;
        int gy = ty0 + r - 7, gx = tx0 + c - 7;
        float v = 0.f;
        if (gy >= 0 && gy < 256 && gx >= 0 && gx < 256)
            v = noise[((size_t)(b * 3 + ic) * 256 + gy) * 256 + gx];
        xs[i] = v;
    }
    __syncthreads();

    float acc[16];
#pragma unroll
    for (int o = 0; o < 16; o++) acc[o] = 0.f;
#pragma unroll
    for (int ic = 0; ic < 3; ic++) {
        const float* xp = xs + ic * 340 + ty * 34 + tx;
        float xv[9];
#pragma unroll
        for (int ky = 0; ky < 3; ky++)
#pragma unroll
            for (int kx = 0; kx < 3; kx++) xv[ky * 3 + kx] = xp[ky * 34 + kx];
        const float4* wp = (const float4*)(ws + ic * 144);
#pragma unroll
        for (int k = 0; k < 9; k++) {
#pragma unroll
            for (int q = 0; q < 4; q++) {
                float4 w4 = wp[k * 4 + q];
                acc[q * 4 + 0] = fmaf(xv[k], w4.x, acc[q * 4 + 0]);
                acc[q * 4 + 1] = fmaf(xv[k], w4.y, acc[q * 4 + 1]);
                acc[q * 4 + 2] = fmaf(xv[k], w4.z, acc[q * 4 + 2]);
                acc[q * 4 + 3] = fmaf(xv[k], w4.w, acc[q * 4 + 3]);
            }
        }
    }

    int ox = tx0 + tx, oy = ty0 + ty;
    if (ox < Sout && oy < Sout) {
        __align__(16) __half h16[16];
#pragma unroll
        for (int o = 0; o < 16; o++) {
            float v = acc[o] * cw + hb[b * 64 + oc0 + o] * cb;
            v = v > 0.f ? v : 0.02f * v;
            h16[o] = __float2half_rn(v);
        }
        size_t obase = ((size_t)b * (Sout * Sout) + (size_t)oy * Sout + ox) * 64 + oc0;
        uint4* dh = (uint4*)(oh + obase);
        dh[0] = ((uint4*)h16)[0]; dh[1] = ((uint4*)h16)[1];
    }
}

// ---------------- A-slab gather via cp.async (10x18 slab) --------------------
__device__ __forceinline__ void gather_tile(uint32_t dst,
                                            const __half* __restrict__ src,
                                            int oy0, int ox0, int Sin, int tid)
{
    for (int i = tid; i < 1440; i += NTHR) {
        int e = i >> 3, q = i & 7;
        int er = e / 18, ec = e - er * 18;
        int iy = oy0 + er; if (iy > Sin - 1) iy = Sin - 1;
        int ix = ox0 + ec; if (ix > Sin - 1) ix = Sin - 1;
        size_t base = ((size_t)iy * Sin + ix) * 64 + q * 8;
        cp16(dst + swz((uint32_t)(e * 128 + q * 16)), src + base);
    }
    CP_COMMIT();
}

// ---------------- body (mma.sync fp16, N-split: 2 CTAs/SM) -------------------
__global__ __launch_bounds__(NTHR, 2)
void body_mma_kernel(const __half* __restrict__ in_a,
                     const __half* __restrict__ wt,     // [16][9][64 ic][64 oc]
                     const float* __restrict__ bias,    // [16][64]
                     __half* __restrict__ out_a,
                     int Sin, float cb)
{
    extern __shared__ __align__(1024) char smem[];
    const int Sout = Sin - 2;
    const int b = blockIdx.z;
    const int slot = blockIdx.x >> 1;        // 0..8
    const int half = blockIdx.x & 1;         // oc half: 0 -> oc 0-31, 1 -> oc 32-63
    const int tid = threadIdx.x, wid = tid >> 5, lane = tid & 31;
    const int wm = wid & 3, wn = wid >> 2;    // 4 row-groups x 2 oc-sub (16 oc each)
    uint32_t sbase = smem_u32(smem);
    const uint32_t A[2] = { sbase + SM_A0, sbase + SM_A1 };

    // stage this CTA's weight half: [tap][ic 64][64B oc32], SW64-swizzled
    {
        const __half* wb = wt + (size_t)b * 9 * 4096 + half * 32;
        for (int i = tid; i < 2304; i += NTHR) {   // 9 tap x 64 ic x 4 chunks
            int q = i & 3, ic = (i >> 2) & 63, tap = i >> 8;
            const uint4* src = (const uint4*)(wb + ((size_t)tap * 64 + ic) * 64 + q * 8);
            *(uint4*)(smem + SM_WS + tap * 4096 + swz64(ic * 64 + q * 16)) = *src;
        }
    }

    float bv[4];
#pragma unroll
    for (int j = 0; j < 2; j++) {
        int oc = half * 32 + wn * 16 + j * 8 + (lane & 3) * 2;
        bv[j * 2 + 0] = bias[b * 64 + oc] * cb;
        bv[j * 2 + 1] = bias[b * 64 + oc + 1] * cb;
    }

    const __half* ia = in_a + (size_t)b * Sin * Sin * 64;
    const int nrt = (Sout + 7) >> 3, nct = (Sout + 15) >> 4;
    const int ntiles = nrt * nct;
    const size_t Spo = (size_t)Sout * Sout;

    const int laneA = (lane & 15) * 128 + (lane >> 4) * 16;
    const int laneB = (lane & 15) * 64 + (lane >> 4) * 16 + wn * 32;

    int s = 0;
    {
        int t0 = slot;
        if (t0 < ntiles) {
            int rt = t0 / nct, ct = t0 - rt * nct;
            gather_tile(A[0], ia, rt * 8, ct * 16, Sin, tid);
        } else {
            CP_COMMIT();
        }
    }

    for (int tt = slot; tt < ntiles; tt += 9) {
        int rt = tt / nct, ct = tt - rt * nct;
        int oy0 = rt * 8, ox0 = ct * 16;

        __syncthreads();
        int tn = tt + 9;
        if (tn < ntiles) {
            int rtn = tn / nct, ctn = tn - rtn * nct;
            gather_tile(A[s ^ 1], ia, rtn * 8, ctn * 16, Sin, tid);
        } else {
            CP_COMMIT();
        }
        CP_WAIT(1); __syncthreads();

        float acc[2][2][4];
#pragma unroll
        for (int mt = 0; mt < 2; mt++)
#pragma unroll
            for (int j = 0; j < 2; j++)
#pragma unroll
                for (int r = 0; r < 4; r++) acc[mt][j][r] = 0.f;

#pragma unroll
        for (int ky = 0; ky < 3; ky++) {
#pragma unroll
            for (int kx = 0; kx < 3; kx++) {
                uint32_t wtile = sbase + SM_WS + (ky * 3 + kx) * 4096;
#pragma unroll
                for (int kc = 0; kc < 4; kc++) {
                    uint32_t a_f[2][4];
#pragma unroll
                    for (int mt = 0; mt < 2; mt++) {
                        int ebase = ((wm * 2 + mt + ky) * 18 + kx) * 128 + kc * 32;
                        ldsm4(a_f[mt], A[s] + swz((uint32_t)(ebase + laneA)));
                    }
                    uint32_t bf[4];
                    ldsm4t(bf, wtile + swz64((uint32_t)(kc * 1024 + laneB)));
#pragma unroll
                    for (int mt = 0; mt < 2; mt++) {
#pragma unroll
                        for (int j = 0; j < 2; j++) {
                            mma16816(acc[mt][j], a_f[mt], bf[j * 2], bf[j * 2 + 1]);
                        }
                    }
                }
            }
        }

        // epilogue: bias + leaky, store fp16 (this CTA's 32 oc)
#pragma unroll
        for (int mt = 0; mt < 2; mt++) {
            int oy = oy0 + wm * 2 + mt;
            if (oy >= Sout) continue;
#pragma unroll
            for (int rs = 0; rs < 2; rs++) {
                int c = (lane >> 2) + rs * 8;
                int ox = ox0 + c;
                if (ox >= Sout) continue;
                size_t pix = (size_t)oy * Sout + ox;
                size_t eoff = ((size_t)b * Spo + pix) * 64 + half * 32 + wn * 16 + (lane & 3) * 2;
#pragma unroll
                for (int j = 0; j < 2; j++) {
                    float v0 = acc[mt][j][rs * 2 + 0] + bv[j * 2 + 0];
                    float v1 = acc[mt][j][rs * 2 + 1] + bv[j * 2 + 1];
                    v0 = v0 > 0.f ? v0 : 0.02f * v0;
                    v1 = v1 > 0.f ? v1 : 0.02f * v1;
                    __half h0 = __float2half_rn(v0);
                    __half h1 = __float2half_rn(v1);
                    unsigned ph = (unsigned)__half_as_ushort(h0) | ((unsigned)__half_as_ushort(h1) << 16);
                    *(unsigned*)(out_a + eoff + j * 8) = ph;
                }
            }
        }
        s ^= 1;
    }
}

// ---------------- tail (mma, N=8 padded from 3, tanh epilogue) ---------------
__global__ __launch_bounds__(NTHR, 2)
void tail_mma_kernel(const __half* __restrict__ in_a,
                     const float* __restrict__ bias,    // [16][3]
                     float* __restrict__ out, float cb)
{
    extern __shared__ __align__(1024) char smem[];
    const int Sin = 258, Sout = 256;
    const int b = blockIdx.z, slot = blockIdx.x, nslots = gridDim.x;
    const int tid = threadIdx.x, wid = tid >> 5, lane = tid & 31;
    uint32_t sbase = smem_u32(smem);
    const uint32_t A[2] = { sbase + TSM_A0, sbase + TSM_A1 };

    // stage tail weights: [tap][ic 64][oc8] fp16, 16B rows
    {
        const __half* wb = g_twt + (size_t)b * 9 * 512;
        for (int i = tid; i < 576; i += NTHR) {
            *(uint4*)(smem + TSM_WS + i * 16) = *((const uint4*)wb + i);
        }
    }

    const __half* ia = in_a + (size_t)b * Sin * Sin * 64;
    const int nct = 16, ntiles = 32 * 16;    // 8x16 px tiles over 256x256

    const int laneA = (lane & 15) * 128 + (lane >> 4) * 16;

    int s = 0;
    {
        int t0 = slot;
        if (t0 < ntiles) {
            int rt = t0 / nct, ct = t0 - rt * nct;
            gather_tile(A[0], ia, rt * 8, ct * 16, Sin, tid);
        } else {
            CP_COMMIT();
        }
    }

    for (int tt = slot; tt < ntiles; tt += nslots) {
        int rt = tt / nct, ct = tt - rt * nct;
        int oy0 = rt * 8, ox0 = ct * 16;

        __syncthreads();
        int tn = tt + nslots;
        if (tn < ntiles) {
            int rtn = tn / nct, ctn = tn - rtn * nct;
            gather_tile(A[s ^ 1], ia, rtn * 8, ctn * 16, Sin, tid);
        } else {
            CP_COMMIT();
        }
        CP_WAIT(1); __syncthreads();

        float acc[4] = {0.f, 0.f, 0.f, 0.f};

#pragma unroll
        for (int ky = 0; ky < 3; ky++) {
#pragma unroll
            for (int kx = 0; kx < 3; kx++) {
                uint32_t wtap = sbase + TSM_WS + (ky * 3 + kx) * 1024;
#pragma unroll
                for (int kh = 0; kh < 2; kh++) {
                    uint32_t bf[4];
                    ldsm4t(bf, wtap + kh * 512 + lane * 16);
#pragma unroll
                    for (int wh = 0; wh < 2; wh++) {
                        int kc = kh * 2 + wh;
                        int ebase = ((wid + ky) * 18 + kx) * 128 + kc * 32;
                        uint32_t a_f[4];
                        ldsm4(a_f, A[s] + swz((uint32_t)(ebase + laneA)));
                        mma16816(acc, a_f, bf[wh * 2], bf[wh * 2 + 1]);
                    }
                }
            }
        }

        // epilogue: tanh(acc + bias)
        {
            int oy = oy0 + wid;
            int oc0 = (lane & 3) * 2;
            if (oc0 < 3) {
                int p0 = lane >> 2;
#pragma unroll
                for (int rs = 0; rs < 2; rs++) {
                    int ox = ox0 + p0 + rs * 8;
                    float v0 = acc[rs * 2 + 0] + bias[b * 3 + oc0] * cb;
                    out[((size_t)(b * 3 + oc0) * Sout + oy) * Sout + ox] = tanhf(v0);
                    if (oc0 + 1 < 3) {
                        float v1 = acc[rs * 2 + 1] + bias[b * 3 + oc0 + 1] * cb;
                        out[((size_t)(b * 3 + oc0 + 1) * Sout + oy) * Sout + ox] = tanhf(v1);
                    }
                }
            }
        }
        s ^= 1;
    }
}

// ---------------- launch ----------------
extern "C" void kernel_launch(void* const* d_in, const int* in_sizes, int n_in,
                              void* d_out, int out_size)
{
    const float* noise  = (const float*)d_in[0];
    const float* head_w = (const float*)d_in[1];
    const float* head_b = (const float*)d_in[2];
    const float* body_w = (const float*)d_in[3];
    const float* body_b = (const float*)d_in[4];
    const float* tail_w = (const float*)d_in[5];
    const float* tail_b = (const float*)d_in[6];
    float* out = (float*)d_out;

    __half *actA, *actB, *wt;
    cudaGetSymbolAddress((void**)&actA, g_actA);
    cudaGetSymbolAddress((void**)&actB, g_actB);
    cudaGetSymbolAddress((void**)&wt, g_wt);

    cudaFuncSetAttribute(body_mma_kernel, cudaFuncAttributeMaxDynamicSharedMemorySize, SMEM_BODY);
    cudaFuncSetAttribute(tail_mma_kernel, cudaFuncAttributeMaxDynamicSharedMemorySize, SMEM_TAIL);

    const double lr_gain = sqrt(2.0 / (1.0 + 0.02 * 0.02));
    const float cw_head = (float)(lr_gain / sqrt(27.0));
    const float cb_head = (float)(1.0 / sqrt(3.0));
    const float cw_body = (float)(lr_gain / 24.0);
    const float cb_body = 0.125f;
    const float cw_tail = (float)((5.0 / 3.0) / 24.0);
    const float cb_tail = 0.125f;

    // weight preps (fold cw, fp16, k-major)
    {
        int N = 5 * 16 * 9 * 64 * 64;
        prep_kernel<<<(N + 255) / 256, 256>>>(body_w, cw_body);
        int M = 16 * 9 * 64 * 8;
        prep_tail_kernel<<<(M + 255) / 256, 256>>>(tail_w, cw_tail);
    }

    // head -> actA (268)
    {
        dim3 grid((268 + 31) / 32, (268 + 7) / 8, BATCH * 4);
        head_kernel<<<grid, 256>>>(noise, head_w, head_b, actA, cw_head, cb_head);
    }

    // 5 body layers, ping-pong; grid = 9 slots x 2 oc-halves per batch
    __half *src = actA, *dst = actB;
    int Sin = 268;
    for (int l = 0; l < 5; l++) {
        dim3 grid(18, 1, BATCH);
        const __half* wt_l = wt + (size_t)l * 16 * 9 * 4096;
        const float* bias_l = body_b + (size_t)l * 16 * 64;
        body_mma_kernel<<<grid, NTHR, SMEM_BODY>>>(src, wt_l, bias_l, dst, Sin, cb_body);
        __half* t = src; src = dst; dst = t;
        Sin -= 2;
    }

    // tail (tensorized): src 258 -> out 256
    {
        dim3 grid(36, 1, BATCH);
        tail_mma_kernel<<<grid, NTHR, SMEM_TAIL>>>(src, tail_b, out, cb_tail);
    }
}

// round 15
// speedup vs baseline: 1.0780x; 1.0780x over previous
#include <cuda_runtime.h>
#include <cuda_fp16.h>
#include <math.h>
#include <stdint.h>

#define BATCH 16
#define MAXPIX (268u * 268u)

// activations NHWC fp16 (single precision-term), ping-pong
__device__ __half g_actA[16u * MAXPIX * 64u];
__device__ __half g_actB[16u * MAXPIX * 64u];
// fp16 body weights, K-MAJOR: [5][16][tap 9][ic 64][oc 64]
__device__ __half g_wt[5u * 16u * 9u * 64u * 64u];
// fp16 tail weights: [16][tap 9][ic 64][oc 8(pad)]
__device__ __half g_twt[16u * 9u * 64u * 8u];

// ---------------- helpers ----------------
__device__ __forceinline__ uint32_t smem_u32(const void* p) {
    uint32_t a;
    asm("{ .reg .u64 t; cvta.to.shared.u64 t, %1; cvt.u32.u64 %0, t; }" : "=r"(a) : "l"(p));
    return a;
}
__device__ __forceinline__ uint32_t swz(uint32_t o) { return o ^ ((o >> 3) & 0x70); }

__device__ __forceinline__ void ldsm4(uint32_t r[4], uint32_t addr) {
    asm volatile("ldmatrix.sync.aligned.m8n8.x4.shared.b16 {%0,%1,%2,%3}, [%4];"
        : "=r"(r[0]), "=r"(r[1]), "=r"(r[2]), "=r"(r[3]) : "r"(addr));
}
__device__ __forceinline__ void ldsm4t(uint32_t r[4], uint32_t addr) {
    asm volatile("ldmatrix.sync.aligned.m8n8.x4.trans.shared.b16 {%0,%1,%2,%3}, [%4];"
        : "=r"(r[0]), "=r"(r[1]), "=r"(r[2]), "=r"(r[3]) : "r"(addr));
}
__device__ __forceinline__ void mma16816(float d[4], const uint32_t a[4], uint32_t b0, uint32_t b1) {
    asm volatile("mma.sync.aligned.m16n8k16.row.col.f32.f16.f16.f32 "
        "{%0,%1,%2,%3}, {%4,%5,%6,%7}, {%8,%9}, {%0,%1,%2,%3};"
        : "+f"(d[0]), "+f"(d[1]), "+f"(d[2]), "+f"(d[3])
        : "r"(a[0]), "r"(a[1]), "r"(a[2]), "r"(a[3]), "r"(b0), "r"(b1));
}
__device__ __forceinline__ void cp16(uint32_t dst, const void* src) {
    asm volatile("cp.async.cg.shared.global [%0], [%1], 16;" :: "r"(dst), "l"(src) : "memory");
}
#define CP_COMMIT() asm volatile("cp.async.commit_group;" ::: "memory")
#define CP_WAIT(n)  asm volatile("cp.async.wait_group %0;" :: "n"(n) : "memory")

// smem layout for body kernel (8x16 px tile -> 10x18 slab)
#define SM_WS   0          // 9 x 8192 = 73728
#define SM_A0   73728
#define SM_A1   97280
#define SMEM_BODY 120832

// smem layout for tail kernel (8x16 px tile, 10x18 slab)
#define TSM_WS  0          // 9 x 1024 = 9216
#define TSM_A0  9216
#define TSM_A1  32768
#define SMEM_TAIL 56320

#define NTHR 256
#define NREGTAPS 4         // taps 0..3 keep B fragments register-resident

// ---------------- weight prep: [l][b][tap][ic][oc], cw folded, fp16 ----------
__global__ void prep_kernel(const float* __restrict__ bw, float cw) {
    int idx = blockIdx.x * blockDim.x + threadIdx.x;
    const int N = 5 * 16 * 9 * 64 * 64;
    if (idx >= N) return;
    int oc = idx & 63;
    int ic = (idx >> 6) & 63;
    int tap = (idx >> 12) % 9;
    int rest = idx / (9 * 64 * 64);   // l*16+b
    float v = bw[(((size_t)rest * 64 + oc) * 64 + ic) * 9 + tap] * cw;
    g_wt[idx] = __float2half_rn(v);
}

// tail weights: [b][tap][ic][oc8], cw folded, oc>=3 zero
__global__ void prep_tail_kernel(const float* __restrict__ tw, float cw) {
    int idx = blockIdx.x * blockDim.x + threadIdx.x;
    const int N = 16 * 9 * 64 * 8;
    if (idx >= N) return;
    int oc = idx & 7;
    int ic = (idx >> 3) & 63;
    int tap = (idx >> 9) % 9;
    int b = idx / (9 * 64 * 8);
    float v = 0.f;
    if (oc < 3) v = tw[(((size_t)b * 3 + oc) * 64 + ic) * 9 + tap] * cw;
    g_twt[idx] = __float2half_rn(v);
}

// ---------------- head (scalar fp32, writes NHWC fp16) ----------------
__global__ __launch_bounds__(256)
void head_kernel(const float* __restrict__ noise, const float* __restrict__ hw,
                 const float* __restrict__ hb, __half* __restrict__ oh,
                 float cw, float cb)
{
    const int Sout = 268;
    int b = blockIdx.z >> 2;
    int oc0 = (blockIdx.z & 3) << 4;
    int tx0 = blockIdx.x * 32, ty0 = blockIdx.y * 8;
    int tid = threadIdx.x, tx = tid & 31, ty = tid >> 5;

    __shared__ __align__(16) float ws[3 * 9 * 16];
    __shared__ float xs[3 * 10 * 34];

    for (int i = tid; i < 3 * 144; i += 256) {
        int oc = i & 15, k = (i >> 4) % 9, ic = i / 144;
        ws[i] = hw[((b * 64 + oc0 + oc) * 3 + ic) * 9 + k];
    }
    for (int i = tid; i < 3 * 340; i += 256) {
        int ic = i / 340, rem = i % 340, r = rem / 34, c = rem % 34;
        int gy = ty0 + r - 7, gx = tx0 + c - 7;
        float v = 0.f;
        if (gy >= 0 && gy < 256 && gx >= 0 && gx < 256)
            v = noise[((size_t)(b * 3 + ic) * 256 + gy) * 256 + gx];
        xs[i] = v;
    }
    __syncthreads();

    float acc[16];
#pragma unroll
    for (int o = 0; o < 16; o++) acc[o] = 0.f;
#pragma unroll
    for (int ic = 0; ic < 3; ic++) {
        const float* xp = xs + ic * 340 + ty * 34 + tx;
        float xv[9];
#pragma unroll
        for (int ky = 0; ky < 3; ky++)
#pragma unroll
            for (int kx = 0; kx < 3; kx++) xv[ky * 3 + kx] = xp[ky * 34 + kx];
        const float4* wp = (const float4*)(ws + ic * 144);
#pragma unroll
        for (int k = 0; k < 9; k++) {
#pragma unroll
            for (int q = 0; q < 4; q++) {
                float4 w4 = wp[k * 4 + q];
                acc[q * 4 + 0] = fmaf(xv[k], w4.x, acc[q * 4 + 0]);
                acc[q * 4 + 1] = fmaf(xv[k], w4.y, acc[q * 4 + 1]);
                acc[q * 4 + 2] = fmaf(xv[k], w4.z, acc[q * 4 + 2]);
                acc[q * 4 + 3] = fmaf(xv[k], w4.w, acc[q * 4 + 3]);
            }
        }
    }

    int ox = tx0 + tx, oy = ty0 + ty;
    if (ox < Sout && oy < Sout) {
        __align__(16) __half h16[16];
#pragma unroll
        for (int o = 0; o < 16; o++) {
            float v = acc[o] * cw + hb[b * 64 + oc0 + o] * cb;
            v = v > 0.f ? v : 0.02f * v;
            h16[o] = __float2half_rn(v);
        }
        size_t obase = ((size_t)b * (Sout * Sout) + (size_t)oy * Sout + ox) * 64 + oc0;
        uint4* dh = (uint4*)(oh + obase);
        dh[0] = ((uint4*)h16)[0]; dh[1] = ((uint4*)h16)[1];
    }
}

// ---------------- A-slab gather via cp.async (10x18 slab) --------------------
__device__ __forceinline__ void gather_tile(uint32_t dst,
                                            const __half* __restrict__ src,
                                            int oy0, int ox0, int Sin, int tid)
{
    for (int i = tid; i < 1440; i += NTHR) {
        int e = i >> 3, q = i & 7;
        int er = e / 18, ec = e - er * 18;
        int iy = oy0 + er; if (iy > Sin - 1) iy = Sin - 1;
        int ix = ox0 + ec; if (ix > Sin - 1) ix = Sin - 1;
        size_t base = ((size_t)iy * Sin + ix) * 64 + q * 8;
        cp16(dst + swz((uint32_t)(e * 128 + q * 16)), src + base);
    }
    CP_COMMIT();
}

// ---------------- body (mma.sync fp16, 4 taps' B register-resident) ----------
__global__ __launch_bounds__(NTHR, 1)
void body_mma_kernel(const __half* __restrict__ in_a,
                     const __half* __restrict__ wt,     // [16][9][64 ic][64 oc]
                     const float* __restrict__ bias,    // [16][64]
                     __half* __restrict__ out_a,
                     int Sin, float cb)
{
    extern __shared__ __align__(1024) char smem[];
    const int Sout = Sin - 2;
    const int b = blockIdx.z, slot = blockIdx.x;
    const int tid = threadIdx.x, wid = tid >> 5, lane = tid & 31;
    const int wm = wid & 3, wn = wid >> 2;       // 4 x 2 warp grid, M32 x N32
    uint32_t sbase = smem_u32(smem);
    const uint32_t A[2] = { sbase + SM_A0, sbase + SM_A1 };

    // stage weights: [tap][ic 64][128B oc], SW128-swizzled
    {
        const __half* wb = wt + (size_t)b * 9 * 4096;
        for (int i = tid; i < 4608; i += NTHR) {
            int j = i & 511, tap = i >> 9;
            int ic = j >> 3, q = j & 7;
            const uint4* src = (const uint4*)(wb + ((size_t)tap * 64 + ic) * 64) + q;
            *(uint4*)(smem + SM_WS + tap * 8192 + swz(ic * 128 + q * 16)) = *src;
        }
    }

    float bv[8];
#pragma unroll
    for (int j = 0; j < 4; j++) {
        int oc = wn * 32 + j * 8 + (lane & 3) * 2;
        bv[j * 2 + 0] = bias[b * 64 + oc] * cb;
        bv[j * 2 + 1] = bias[b * 64 + oc + 1] * cb;
    }

    const __half* ia = in_a + (size_t)b * Sin * Sin * 64;
    const int nrt = (Sout + 7) >> 3, nct = (Sout + 15) >> 4;
    const int ntiles = nrt * nct;
    const size_t Spo = (size_t)Sout * Sout;

    const int laneA = (lane & 15) * 128 + (lane >> 4) * 16;
    const int laneB = (lane & 15) * 128 + (lane >> 4) * 16 + wn * 64;

    // load taps 0..3's B fragments into registers once (tile-invariant)
    __syncthreads();
    uint32_t breg[NREGTAPS][4][2][4];
#pragma unroll
    for (int tap = 0; tap < NREGTAPS; tap++) {
#pragma unroll
        for (int kc = 0; kc < 4; kc++) {
#pragma unroll
            for (int nt = 0; nt < 2; nt++) {
                ldsm4t(breg[tap][kc][nt],
                       sbase + SM_WS + tap * 8192 + swz((uint32_t)(kc * 2048 + laneB + nt * 32)));
            }
        }
    }

    int s = 0;
    {
        int t0 = slot;
        if (t0 < ntiles) {
            int rt = t0 / nct, ct = t0 - rt * nct;
            gather_tile(A[0], ia, rt * 8, ct * 16, Sin, tid);
        } else {
            CP_COMMIT();
        }
    }

    for (int tt = slot; tt < ntiles; tt += 9) {
        int rt = tt / nct, ct = tt - rt * nct;
        int oy0 = rt * 8, ox0 = ct * 16;

        __syncthreads();
        int tn = tt + 9;
        if (tn < ntiles) {
            int rtn = tn / nct, ctn = tn - rtn * nct;
            gather_tile(A[s ^ 1], ia, rtn * 8, ctn * 16, Sin, tid);
        } else {
            CP_COMMIT();
        }
        CP_WAIT(1); __syncthreads();

        float acc[2][4][4];
#pragma unroll
        for (int mt = 0; mt < 2; mt++)
#pragma unroll
            for (int j = 0; j < 4; j++)
#pragma unroll
                for (int r = 0; r < 4; r++) acc[mt][j][r] = 0.f;

#pragma unroll
        for (int tap = 0; tap < 9; tap++) {
            const int ky = tap / 3, kx = tap % 3;
            uint32_t wtile = sbase + SM_WS + tap * 8192;
#pragma unroll
            for (int kc = 0; kc < 4; kc++) {
                uint32_t a_f[2][4];
#pragma unroll
                for (int mt = 0; mt < 2; mt++) {
                    int ebase = ((wm * 2 + mt + ky) * 18 + kx) * 128 + kc * 32;
                    ldsm4(a_f[mt], A[s] + swz((uint32_t)(ebase + laneA)));
                }
                uint32_t bf[2][4];
                if (tap < NREGTAPS) {
#pragma unroll
                    for (int nt = 0; nt < 2; nt++)
#pragma unroll
                        for (int r = 0; r < 4; r++) bf[nt][r] = breg[tap][kc][nt][r];
                } else {
#pragma unroll
                    for (int nt = 0; nt < 2; nt++) {
                        uint32_t off = swz((uint32_t)(kc * 2048 + laneB + nt * 32));
                        ldsm4t(bf[nt], wtile + off);
                    }
                }
#pragma unroll
                for (int mt = 0; mt < 2; mt++) {
#pragma unroll
                    for (int j = 0; j < 4; j++) {
                        uint32_t b0 = bf[j >> 1][(j & 1) * 2];
                        uint32_t b1 = bf[j >> 1][(j & 1) * 2 + 1];
                        mma16816(acc[mt][j], a_f[mt], b0, b1);
                    }
                }
            }
        }

        // epilogue: bias + leaky, store fp16
#pragma unroll
        for (int mt = 0; mt < 2; mt++) {
            int oy = oy0 + wm * 2 + mt;
            if (oy >= Sout) continue;
#pragma unroll
            for (int rs = 0; rs < 2; rs++) {
                int c = (lane >> 2) + rs * 8;
                int ox = ox0 + c;
                if (ox >= Sout) continue;
                size_t pix = (size_t)oy * Sout + ox;
                size_t eoff = ((size_t)b * Spo + pix) * 64 + wn * 32 + (lane & 3) * 2;
#pragma unroll
                for (int j = 0; j < 4; j++) {
                    float v0 = acc[mt][j][rs * 2 + 0] + bv[j * 2 + 0];
                    float v1 = acc[mt][j][rs * 2 + 1] + bv[j * 2 + 1];
                    v0 = v0 > 0.f ? v0 : 0.02f * v0;
                    v1 = v1 > 0.f ? v1 : 0.02f * v1;
                    __half h0 = __float2half_rn(v0);
                    __half h1 = __float2half_rn(v1);
                    unsigned ph = (unsigned)__half_as_ushort(h0) | ((unsigned)__half_as_ushort(h1) << 16);
                    *(unsigned*)(out_a + eoff + j * 8) = ph;
                }
            }
        }
        s ^= 1;
    }
}

// ---------------- tail (mma, N=8 padded from 3, tanh epilogue) ---------------
__global__ __launch_bounds__(NTHR, 2)
void tail_mma_kernel(const __half* __restrict__ in_a,
                     const float* __restrict__ bias,    // [16][3]
                     float* __restrict__ out, float cb)
{
    extern __shared__ __align__(1024) char smem[];
    const int Sin = 258, Sout = 256;
    const int b = blockIdx.z, slot = blockIdx.x, nslots = gridDim.x;
    const int tid = threadIdx.x, wid = tid >> 5, lane = tid & 31;
    uint32_t sbase = smem_u32(smem);
    const uint32_t A[2] = { sbase + TSM_A0, sbase + TSM_A1 };

    // stage tail weights: [tap][ic 64][oc8] fp16, 16B rows
    {
        const __half* wb = g_twt + (size_t)b * 9 * 512;
        for (int i = tid; i < 576; i += NTHR) {
            *(uint4*)(smem + TSM_WS + i * 16) = *((const uint4*)wb + i);
        }
    }

    const __half* ia = in_a + (size_t)b * Sin * Sin * 64;
    const int nct = 16, ntiles = 32 * 16;    // 8x16 px tiles over 256x256

    const int laneA = (lane & 15) * 128 + (lane >> 4) * 16;

    int s = 0;
    {
        int t0 = slot;
        if (t0 < ntiles) {
            int rt = t0 / nct, ct = t0 - rt * nct;
            gather_tile(A[0], ia, rt * 8, ct * 16, Sin, tid);
        } else {
            CP_COMMIT();
        }
    }

    for (int tt = slot; tt < ntiles; tt += nslots) {
        int rt = tt / nct, ct = tt - rt * nct;
        int oy0 = rt * 8, ox0 = ct * 16;

        __syncthreads();
        int tn = tt + nslots;
        if (tn < ntiles) {
            int rtn = tn / nct, ctn = tn - rtn * nct;
            gather_tile(A[s ^ 1], ia, rtn * 8, ctn * 16, Sin, tid);
        } else {
            CP_COMMIT();
        }
        CP_WAIT(1); __syncthreads();

        float acc[4] = {0.f, 0.f, 0.f, 0.f};

#pragma unroll
        for (int ky = 0; ky < 3; ky++) {
#pragma unroll
            for (int kx = 0; kx < 3; kx++) {
                uint32_t wtap = sbase + TSM_WS + (ky * 3 + kx) * 1024;
#pragma unroll
                for (int kh = 0; kh < 2; kh++) {
                    uint32_t bf[4];
                    ldsm4t(bf, wtap + kh * 512 + lane * 16);
#pragma unroll
                    for (int wh = 0; wh < 2; wh++) {
                        int kc = kh * 2 + wh;
                        int ebase = ((wid + ky) * 18 + kx) * 128 + kc * 32;
                        uint32_t a_f[4];
                        ldsm4(a_f, A[s] + swz((uint32_t)(ebase + laneA)));
                        mma16816(acc, a_f, bf[wh * 2], bf[wh * 2 + 1]);
                    }
                }
            }
        }

        // epilogue: tanh(acc + bias)
        {
            int oy = oy0 + wid;
            int oc0 = (lane & 3) * 2;
            if (oc0 < 3) {
                int p0 = lane >> 2;
#pragma unroll
                for (int rs = 0; rs < 2; rs++) {
                    int ox = ox0 + p0 + rs * 8;
                    float v0 = acc[rs * 2 + 0] + bias[b * 3 + oc0] * cb;
                    out[((size_t)(b * 3 + oc0) * Sout + oy) * Sout + ox] = tanhf(v0);
                    if (oc0 + 1 < 3) {
                        float v1 = acc[rs * 2 + 1] + bias[b * 3 + oc0 + 1] * cb;
                        out[((size_t)(b * 3 + oc0 + 1) * Sout + oy) * Sout + ox] = tanhf(v1);
                    }
                }
            }
        }
        s ^= 1;
    }
}

// ---------------- launch ----------------
extern "C" void kernel_launch(void* const* d_in, const int* in_sizes, int n_in,
                              void* d_out, int out_size)
{
    const float* noise  = (const float*)d_in[0];
    const float* head_w = (const float*)d_in[1];
    const float* head_b = (const float*)d_in[2];
    const float* body_w = (const float*)d_in[3];
    const float* body_b = (const float*)d_in[4];
    const float* tail_w = (const float*)d_in[5];
    const float* tail_b = (const float*)d_in[6];
    float* out = (float*)d_out;

    __half *actA, *actB, *wt;
    cudaGetSymbolAddress((void**)&actA, g_actA);
    cudaGetSymbolAddress((void**)&actB, g_actB);
    cudaGetSymbolAddress((void**)&wt, g_wt);

    cudaFuncSetAttribute(body_mma_kernel, cudaFuncAttributeMaxDynamicSharedMemorySize, SMEM_BODY);
    cudaFuncSetAttribute(tail_mma_kernel, cudaFuncAttributeMaxDynamicSharedMemorySize, SMEM_TAIL);

    const double lr_gain = sqrt(2.0 / (1.0 + 0.02 * 0.02));
    const float cw_head = (float)(lr_gain / sqrt(27.0));
    const float cb_head = (float)(1.0 / sqrt(3.0));
    const float cw_body = (float)(lr_gain / 24.0);
    const float cb_body = 0.125f;
    const float cw_tail = (float)((5.0 / 3.0) / 24.0);
    const float cb_tail = 0.125f;

    // weight preps (fold cw, fp16, k-major)
    {
        int N = 5 * 16 * 9 * 64 * 64;
        prep_kernel<<<(N + 255) / 256, 256>>>(body_w, cw_body);
        int M = 16 * 9 * 64 * 8;
        prep_tail_kernel<<<(M + 255) / 256, 256>>>(tail_w, cw_tail);
    }

    // head -> actA (268)
    {
        dim3 grid((268 + 31) / 32, (268 + 7) / 8, BATCH * 4);
        head_kernel<<<grid, 256>>>(noise, head_w, head_b, actA, cw_head, cb_head);
    }

    // 5 body layers, ping-pong
    __half *src = actA, *dst = actB;
    int Sin = 268;
    for (int l = 0; l < 5; l++) {
        dim3 grid(9, 1, BATCH);
        const __half* wt_l = wt + (size_t)l * 16 * 9 * 4096;
        const float* bias_l = body_b + (size_t)l * 16 * 64;
        body_mma_kernel<<<grid, NTHR, SMEM_BODY>>>(src, wt_l, bias_l, dst, Sin, cb_body);
        __half* t = src; src = dst; dst = t;
        Sin -= 2;
    }

    // tail (tensorized): src 258 -> out 256
    {
        dim3 grid(36, 1, BATCH);
        tail_mma_kernel<<<grid, NTHR, SMEM_TAIL>>>(src, tail_b, out, cb_tail);
    }
}

// round 17
// speedup vs baseline: 1.1343x; 1.0522x over previous
#include <cuda_runtime.h>
#include <cuda_fp16.h>
#include <math.h>
#include <stdint.h>

#define BATCH 16
#define MAXPIX (268u * 268u)

// activations NHWC fp16 (single precision-term), ping-pong
__device__ __half g_actA[16u * MAXPIX * 64u];
__device__ __half g_actB[16u * MAXPIX * 64u];
// fp16 body weights, K-MAJOR: [5][16][tap 9][ic 64][oc 64]
__device__ __half g_wt[5u * 16u * 9u * 64u * 64u];
// fp16 tail weights: [16][tap 9][ic 64][oc 8(pad)]
__device__ __half g_twt[16u * 9u * 64u * 8u];
// padded fp16 noise for head im2col: [16][270][270][8ch] (ch 3..7 zero)
__device__ __half g_pn[16u * 270u * 270u * 8u];
// head weights for GEMM: [16][80 k][64 oc], k = tap*8+ic, zeros padded
__device__ __half g_hwt[16u * 80u * 64u];

// ---------------- helpers ----------------
__device__ __forceinline__ uint32_t smem_u32(const void* p) {
    uint32_t a;
    asm("{ .reg .u64 t; cvta.to.shared.u64 t, %1; cvt.u32.u64 %0, t; }" : "=r"(a) : "l"(p));
    return a;
}
__device__ __forceinline__ uint32_t swz(uint32_t o) { return o ^ ((o >> 3) & 0x70); }

__device__ __forceinline__ void ldsm4(uint32_t r[4], uint32_t addr) {
    asm volatile("ldmatrix.sync.aligned.m8n8.x4.shared.b16 {%0,%1,%2,%3}, [%4];"
        : "=r"(r[0]), "=r"(r[1]), "=r"(r[2]), "=r"(r[3]) : "r"(addr));
}
__device__ __forceinline__ void ldsm4t(uint32_t r[4], uint32_t addr) {
    asm volatile("ldmatrix.sync.aligned.m8n8.x4.trans.shared.b16 {%0,%1,%2,%3}, [%4];"
        : "=r"(r[0]), "=r"(r[1]), "=r"(r[2]), "=r"(r[3]) : "r"(addr));
}
__device__ __forceinline__ void mma16816(float d[4], const uint32_t a[4], uint32_t b0, uint32_t b1) {
    asm volatile("mma.sync.aligned.m16n8k16.row.col.f32.f16.f16.f32 "
        "{%0,%1,%2,%3}, {%4,%5,%6,%7}, {%8,%9}, {%0,%1,%2,%3};"
        : "+f"(d[0]), "+f"(d[1]), "+f"(d[2]), "+f"(d[3])
        : "r"(a[0]), "r"(a[1]), "r"(a[2]), "r"(a[3]), "r"(b0), "r"(b1));
}
__device__ __forceinline__ void cp16(uint32_t dst, const void* src) {
    asm volatile("cp.async.cg.shared.global [%0], [%1], 16;" :: "r"(dst), "l"(src) : "memory");
}
#define CP_COMMIT() asm volatile("cp.async.commit_group;" ::: "memory")
#define CP_WAIT(n)  asm volatile("cp.async.wait_group %0;" :: "n"(n) : "memory")

// smem layout for body kernel (8x16 px tile -> 10x18 slab)
#define SM_WS   0          // 9 x 8192 = 73728
#define SM_A0   73728
#define SM_A1   97280
#define SMEM_BODY 120832

// smem layout for tail kernel
#define TSM_WS  0          // 9 x 1024 = 9216
#define TSM_A0  9216
#define TSM_A1  32768
#define SMEM_TAIL 56320

// smem layout for head kernel
#define HSM_WS  0          // 80 k x 128B = 10240
#define HSM_A   10240      // 128 rows x 176B = 22528
#define SMEM_HEAD 33792

#define NTHR 256
#define NREGTAPS 4

// ---------------- body weight prep ----------------
__global__ void prep_kernel(const float* __restrict__ bw, float cw) {
    int idx = blockIdx.x * blockDim.x + threadIdx.x;
    const int N = 5 * 16 * 9 * 64 * 64;
    if (idx >= N) return;
    int oc = idx & 63;
    int ic = (idx >> 6) & 63;
    int tap = (idx >> 12) % 9;
    int rest = idx / (9 * 64 * 64);
    float v = bw[(((size_t)rest * 64 + oc) * 64 + ic) * 9 + tap] * cw;
    g_wt[idx] = __float2half_rn(v);
}

// tail weights
__global__ void prep_tail_kernel(const float* __restrict__ tw, float cw) {
    int idx = blockIdx.x * blockDim.x + threadIdx.x;
    const int N = 16 * 9 * 64 * 8;
    if (idx >= N) return;
    int oc = idx & 7;
    int ic = (idx >> 3) & 63;
    int tap = (idx >> 9) % 9;
    int b = idx / (9 * 64 * 8);
    float v = 0.f;
    if (oc < 3) v = tw[(((size_t)b * 3 + oc) * 64 + ic) * 9 + tap] * cw;
    g_twt[idx] = __float2half_rn(v);
}

// padded noise: [b][y 270][x 270][8], fp16, zero halo + zero ch>=3
__global__ void prep_pad_kernel(const float* __restrict__ noise) {
    int idx = blockIdx.x * blockDim.x + threadIdx.x;
    const int N = 16 * 270 * 270;
    if (idx >= N) return;
    int x = idx % 270;
    int y = (idx / 270) % 270;
    int b = idx / (270 * 270);
    __half v[8];
#pragma unroll
    for (int c = 0; c < 8; c++) v[c] = __float2half_rn(0.f);
    if (y >= 7 && y <= 262 && x >= 7 && x <= 262) {
#pragma unroll
        for (int c = 0; c < 3; c++)
            v[c] = __float2half_rn(noise[((size_t)(b * 3 + c) * 256 + (y - 7)) * 256 + (x - 7)]);
    }
    *(uint4*)(g_pn + (size_t)idx * 8) = *(uint4*)v;
}

// head weights: [b][k 80][oc 64], k = tap*8+ic (tap<9 && ic<3 else 0), cw folded
__global__ void prep_head_kernel(const float* __restrict__ hw, float cw) {
    int idx = blockIdx.x * blockDim.x + threadIdx.x;
    const int N = 16 * 80 * 64;
    if (idx >= N) return;
    int oc = idx & 63;
    int k = (idx >> 6) % 80;
    int b = idx / (80 * 64);
    int tap = k >> 3, ic = k & 7;
    float v = 0.f;
    if (tap < 9 && ic < 3)
        v = hw[((b * 64 + oc) * 3 + ic) * 9 + tap] * cw;
    g_hwt[idx] = __float2half_rn(v);
}

// ---------------- head (mma, im2col K=80) ----------------
__global__ __launch_bounds__(NTHR, 2)
void head_mma_kernel(const float* __restrict__ hb, __half* __restrict__ out_a, float cb)
{
    extern __shared__ __align__(1024) char smem[];
    const int Sout = 268;
    const int nct = 17;
    const int b = blockIdx.z;
    const int rt = blockIdx.x / nct, ct = blockIdx.x - rt * nct;
    const int oy0 = rt * 8, ox0 = ct * 16;
    const int tid = threadIdx.x, wid = tid >> 5, lane = tid & 31;
    const int wm = wid & 3, wn = wid >> 2;
    uint32_t sbase = smem_u32(smem);

    // stage head weights: [k 80][128B oc], SW128
    {
        const __half* wb = g_hwt + (size_t)b * 80 * 64;
        for (int i = tid; i < 640; i += NTHR) {
            int k = i >> 3, q = i & 7;
            const uint4* src = (const uint4*)(wb + (size_t)k * 64) + q;
            *(uint4*)(smem + HSM_WS + swz(k * 128 + q * 16)) = *src;
        }
    }
    // zero pad-tap slot: bytes 144..175 of each 176B row (tap 9 @144..159 + tail)
    for (int i = tid; i < 256; i += NTHR) {
        int r = i >> 1, h = i & 1;
        *(uint4*)(smem + HSM_A + r * 176 + 144 + h * 16) = make_uint4(0u, 0u, 0u, 0u);
    }

    // im2col gather: 128 px x 9 taps, 16B each, from padded noise
    const __half* pn = g_pn + (size_t)b * 270 * 270 * 8;
    for (int i = tid; i < 1152; i += NTHR) {
        int p = i / 9, tap = i - p * 9;
        int r = p >> 4, c = p & 15;
        int ky = tap / 3, kx = tap % 3;
        int y = oy0 + r + ky; if (y > 269) y = 269;
        int x = ox0 + c + kx; if (x > 269) x = 269;
        cp16(sbase + HSM_A + p * 176 + tap * 16, pn + ((size_t)y * 270 + x) * 8);
    }
    CP_COMMIT(); CP_WAIT(0);
    __syncthreads();

    float bv[8];
#pragma unroll
    for (int j = 0; j < 4; j++) {
        int oc = wn * 32 + j * 8 + (lane & 3) * 2;
        bv[j * 2 + 0] = hb[b * 64 + oc] * cb;
        bv[j * 2 + 1] = hb[b * 64 + oc + 1] * cb;
    }

    const int laneB = (lane & 15) * 128 + (lane >> 4) * 16 + wn * 64;
    const uint32_t laneAh = (uint32_t)((lane & 15) * 176 + (lane >> 4) * 16);

    float acc[2][4][4];
#pragma unroll
    for (int mt = 0; mt < 2; mt++)
#pragma unroll
        for (int j = 0; j < 4; j++)
#pragma unroll
            for (int r = 0; r < 4; r++) acc[mt][j][r] = 0.f;

#pragma unroll
    for (int kc = 0; kc < 5; kc++) {
        uint32_t a_f[2][4];
#pragma unroll
        for (int mt = 0; mt < 2; mt++) {
            uint32_t abase = sbase + HSM_A + (uint32_t)((wm * 2 + mt) * 16) * 176 + kc * 32;
            ldsm4(a_f[mt], abase + laneAh);
        }
        uint32_t bf[2][4];
#pragma unroll
        for (int nt = 0; nt < 2; nt++) {
            uint32_t off = swz((uint32_t)(kc * 2048 + laneB + nt * 32));
            ldsm4t(bf[nt], sbase + HSM_WS + off);
        }
#pragma unroll
        for (int mt = 0; mt < 2; mt++) {
#pragma unroll
            for (int j = 0; j < 4; j++) {
                uint32_t b0 = bf[j >> 1][(j & 1) * 2];
                uint32_t b1 = bf[j >> 1][(j & 1) * 2 + 1];
                mma16816(acc[mt][j], a_f[mt], b0, b1);
            }
        }
    }

    // epilogue: bias + leaky, store fp16 NHWC (268)
    const size_t Spo = (size_t)Sout * Sout;
#pragma unroll
    for (int mt = 0; mt < 2; mt++) {
        int oy = oy0 + wm * 2 + mt;
        if (oy >= Sout) continue;
#pragma unroll
        for (int rs = 0; rs < 2; rs++) {
            int c = (lane >> 2) + rs * 8;
            int ox = ox0 + c;
            if (ox >= Sout) continue;
            size_t pix = (size_t)oy * Sout + ox;
            size_t eoff = ((size_t)b * Spo + pix) * 64 + wn * 32 + (lane & 3) * 2;
#pragma unroll
            for (int j = 0; j < 4; j++) {
                float v0 = acc[mt][j][rs * 2 + 0] + bv[j * 2 + 0];
                float v1 = acc[mt][j][rs * 2 + 1] + bv[j * 2 + 1];
                v0 = v0 > 0.f ? v0 : 0.02f * v0;
                v1 = v1 > 0.f ? v1 : 0.02f * v1;
                __half h0 = __float2half_rn(v0);
                __half h1 = __float2half_rn(v1);
                unsigned ph = (unsigned)__half_as_ushort(h0) | ((unsigned)__half_as_ushort(h1) << 16);
                *(unsigned*)(out_a + eoff + j * 8) = ph;
            }
        }
    }
}

// ---------------- A-slab gather via cp.async (10x18 slab) --------------------
__device__ __forceinline__ void gather_tile(uint32_t dst,
                                            const __half* __restrict__ src,
                                            int oy0, int ox0, int Sin, int tid)
{
    for (int i = tid; i < 1440; i += NTHR) {
        int e = i >> 3, q = i & 7;
        int er = e / 18, ec = e - er * 18;
        int iy = oy0 + er; if (iy > Sin - 1) iy = Sin - 1;
        int ix = ox0 + ec; if (ix > Sin - 1) ix = Sin - 1;
        size_t base = ((size_t)iy * Sin + ix) * 64 + q * 8;
        cp16(dst + swz((uint32_t)(e * 128 + q * 16)), src + base);
    }
    CP_COMMIT();
}

// ---------------- body (mma.sync fp16, 4 taps' B register-resident) ----------
__global__ __launch_bounds__(NTHR, 1)
void body_mma_kernel(const __half* __restrict__ in_a,
                     const __half* __restrict__ wt,
                     const float* __restrict__ bias,
                     __half* __restrict__ out_a,
                     int Sin, float cb)
{
    extern __shared__ __align__(1024) char smem[];
    const int Sout = Sin - 2;
    const int b = blockIdx.z, slot = blockIdx.x;
    const int tid = threadIdx.x, wid = tid >> 5, lane = tid & 31;
    const int wm = wid & 3, wn = wid >> 2;
    uint32_t sbase = smem_u32(smem);
    const uint32_t A[2] = { sbase + SM_A0, sbase + SM_A1 };

    {
        const __half* wb = wt + (size_t)b * 9 * 4096;
        for (int i = tid; i < 4608; i += NTHR) {
            int j = i & 511, tap = i >> 9;
            int ic = j >> 3, q = j & 7;
            const uint4* src = (const uint4*)(wb + ((size_t)tap * 64 + ic) * 64) + q;
            *(uint4*)(smem + SM_WS + tap * 8192 + swz(ic * 128 + q * 16)) = *src;
        }
    }

    float bv[8];
#pragma unroll
    for (int j = 0; j < 4; j++) {
        int oc = wn * 32 + j * 8 + (lane & 3) * 2;
        bv[j * 2 + 0] = bias[b * 64 + oc] * cb;
        bv[j * 2 + 1] = bias[b * 64 + oc + 1] * cb;
    }

    const __half* ia = in_a + (size_t)b * Sin * Sin * 64;
    const int nrt = (Sout + 7) >> 3, nct = (Sout + 15) >> 4;
    const int ntiles = nrt * nct;
    const size_t Spo = (size_t)Sout * Sout;

    const int laneA = (lane & 15) * 128 + (lane >> 4) * 16;
    const int laneB = (lane & 15) * 128 + (lane >> 4) * 16 + wn * 64;

    __syncthreads();
    uint32_t breg[NREGTAPS][4][2][4];
#pragma unroll
    for (int tap = 0; tap < NREGTAPS; tap++) {
#pragma unroll
        for (int kc = 0; kc < 4; kc++) {
#pragma unroll
            for (int nt = 0; nt < 2; nt++) {
                ldsm4t(breg[tap][kc][nt],
                       sbase + SM_WS + tap * 8192 + swz((uint32_t)(kc * 2048 + laneB + nt * 32)));
            }
        }
    }

    int s = 0;
    {
        int t0 = slot;
        if (t0 < ntiles) {
            int rt = t0 / nct, ct = t0 - rt * nct;
            gather_tile(A[0], ia, rt * 8, ct * 16, Sin, tid);
        } else {
            CP_COMMIT();
        }
    }

    for (int tt = slot; tt < ntiles; tt += 9) {
        int rt = tt / nct, ct = tt - rt * nct;
        int oy0 = rt * 8, ox0 = ct * 16;

        __syncthreads();
        int tn = tt + 9;
        if (tn < ntiles) {
            int rtn = tn / nct, ctn = tn - rtn * nct;
            gather_tile(A[s ^ 1], ia, rtn * 8, ctn * 16, Sin, tid);
        } else {
            CP_COMMIT();
        }
        CP_WAIT(1); __syncthreads();

        float acc[2][4][4];
#pragma unroll
        for (int mt = 0; mt < 2; mt++)
#pragma unroll
            for (int j = 0; j < 4; j++)
#pragma unroll
                for (int r = 0; r < 4; r++) acc[mt][j][r] = 0.f;

#pragma unroll
        for (int tap = 0; tap < 9; tap++) {
            const int ky = tap / 3, kx = tap % 3;
            uint32_t wtile = sbase + SM_WS + tap * 8192;
#pragma unroll
            for (int kc = 0; kc < 4; kc++) {
                uint32_t a_f[2][4];
#pragma unroll
                for (int mt = 0; mt < 2; mt++) {
                    int ebase = ((wm * 2 + mt + ky) * 18 + kx) * 128 + kc * 32;
                    ldsm4(a_f[mt], A[s] + swz((uint32_t)(ebase + laneA)));
                }
                uint32_t bf[2][4];
                if (tap < NREGTAPS) {
#pragma unroll
                    for (int nt = 0; nt < 2; nt++)
#pragma unroll
                        for (int r = 0; r < 4; r++) bf[nt][r] = breg[tap][kc][nt][r];
                } else {
#pragma unroll
                    for (int nt = 0; nt < 2; nt++) {
                        uint32_t off = swz((uint32_t)(kc * 2048 + laneB + nt * 32));
                        ldsm4t(bf[nt], wtile + off);
                    }
                }
#pragma unroll
                for (int mt = 0; mt < 2; mt++) {
#pragma unroll
                    for (int j = 0; j < 4; j++) {
                        uint32_t b0 = bf[j >> 1][(j & 1) * 2];
                        uint32_t b1 = bf[j >> 1][(j & 1) * 2 + 1];
                        mma16816(acc[mt][j], a_f[mt], b0, b1);
                    }
                }
            }
        }

#pragma unroll
        for (int mt = 0; mt < 2; mt++) {
            int oy = oy0 + wm * 2 + mt;
            if (oy >= Sout) continue;
#pragma unroll
            for (int rs = 0; rs < 2; rs++) {
                int c = (lane >> 2) + rs * 8;
                int ox = ox0 + c;
                if (ox >= Sout) continue;
                size_t pix = (size_t)oy * Sout + ox;
                size_t eoff = ((size_t)b * Spo + pix) * 64 + wn * 32 + (lane & 3) * 2;
#pragma unroll
                for (int j = 0; j < 4; j++) {
                    float v0 = acc[mt][j][rs * 2 + 0] + bv[j * 2 + 0];
                    float v1 = acc[mt][j][rs * 2 + 1] + bv[j * 2 + 1];
                    v0 = v0 > 0.f ? v0 : 0.02f * v0;
                    v1 = v1 > 0.f ? v1 : 0.02f * v1;
                    __half h0 = __float2half_rn(v0);
                    __half h1 = __float2half_rn(v1);
                    unsigned ph = (unsigned)__half_as_ushort(h0) | ((unsigned)__half_as_ushort(h1) << 16);
                    *(unsigned*)(out_a + eoff + j * 8) = ph;
                }
            }
        }
        s ^= 1;
    }
}

// ---------------- tail (mma, N=8 padded from 3, tanh epilogue) ---------------
__global__ __launch_bounds__(NTHR, 2)
void tail_mma_kernel(const __half* __restrict__ in_a,
                     const float* __restrict__ bias,
                     float* __restrict__ out, float cb)
{
    extern __shared__ __align__(1024) char smem[];
    const int Sin = 258, Sout = 256;
    const int b = blockIdx.z, slot = blockIdx.x, nslots = gridDim.x;
    const int tid = threadIdx.x, wid = tid >> 5, lane = tid & 31;
    uint32_t sbase = smem_u32(smem);
    const uint32_t A[2] = { sbase + TSM_A0, sbase + TSM_A1 };

    {
        const __half* wb = g_twt + (size_t)b * 9 * 512;
        for (int i = tid; i < 576; i += NTHR) {
            *(uint4*)(smem + TSM_WS + i * 16) = *((const uint4*)wb + i);
        }
    }

    const __half* ia = in_a + (size_t)b * Sin * Sin * 64;
    const int nct = 16, ntiles = 32 * 16;

    const int laneA = (lane & 15) * 128 + (lane >> 4) * 16;

    int s = 0;
    {
        int t0 = slot;
        if (t0 < ntiles) {
            int rt = t0 / nct, ct = t0 - rt * nct;
            gather_tile(A[0], ia, rt * 8, ct * 16, Sin, tid);
        } else {
            CP_COMMIT();
        }
    }

    for (int tt = slot; tt < ntiles; tt += nslots) {
        int rt = tt / nct, ct = tt - rt * nct;
        int oy0 = rt * 8, ox0 = ct * 16;

        __syncthreads();
        int tn = tt + nslots;
        if (tn < ntiles) {
            int rtn = tn / nct, ctn = tn - rtn * nct;
            gather_tile(A[s ^ 1], ia, rtn * 8, ctn * 16, Sin, tid);
        } else {
            CP_COMMIT();
        }
        CP_WAIT(1); __syncthreads();

        float acc[4] = {0.f, 0.f, 0.f, 0.f};

#pragma unroll
        for (int ky = 0; ky < 3; ky++) {
#pragma unroll
            for (int kx = 0; kx < 3; kx++) {
                uint32_t wtap = sbase + TSM_WS + (ky * 3 + kx) * 1024;
#pragma unroll
                for (int kh = 0; kh < 2; kh++) {
                    uint32_t bf[4];
                    ldsm4t(bf, wtap + kh * 512 + lane * 16);
#pragma unroll
                    for (int wh = 0; wh < 2; wh++) {
                        int kc = kh * 2 + wh;
                        int ebase = ((wid + ky) * 18 + kx) * 128 + kc * 32;
                        uint32_t a_f[4];
                        ldsm4(a_f, A[s] + swz((uint32_t)(ebase + laneA)));
                        mma16816(acc, a_f, bf[wh * 2], bf[wh * 2 + 1]);
                    }
                }
            }
        }

        {
            int oy = oy0 + wid;
            int oc0 = (lane & 3) * 2;
            if (oc0 < 3) {
                int p0 = lane >> 2;
#pragma unroll
                for (int rs = 0; rs < 2; rs++) {
                    int ox = ox0 + p0 + rs * 8;
                    float v0 = acc[rs * 2 + 0] + bias[b * 3 + oc0] * cb;
                    out[((size_t)(b * 3 + oc0) * Sout + oy) * Sout + ox] = tanhf(v0);
                    if (oc0 + 1 < 3) {
                        float v1 = acc[rs * 2 + 1] + bias[b * 3 + oc0 + 1] * cb;
                        out[((size_t)(b * 3 + oc0 + 1) * Sout + oy) * Sout + ox] = tanhf(v1);
                    }
                }
            }
        }
        s ^= 1;
    }
}

// ---------------- launch ----------------
extern "C" void kernel_launch(void* const* d_in, const int* in_sizes, int n_in,
                              void* d_out, int out_size)
{
    const float* noise  = (const float*)d_in[0];
    const float* head_w = (const float*)d_in[1];
    const float* head_b = (const float*)d_in[2];
    const float* body_w = (const float*)d_in[3];
    const float* body_b = (const float*)d_in[4];
    const float* tail_w = (const float*)d_in[5];
    const float* tail_b = (const float*)d_in[6];
    float* out = (float*)d_out;

    __half *actA, *actB, *wt;
    cudaGetSymbolAddress((void**)&actA, g_actA);
    cudaGetSymbolAddress((void**)&actB, g_actB);
    cudaGetSymbolAddress((void**)&wt, g_wt);

    cudaFuncSetAttribute(body_mma_kernel, cudaFuncAttributeMaxDynamicSharedMemorySize, SMEM_BODY);
    cudaFuncSetAttribute(tail_mma_kernel, cudaFuncAttributeMaxDynamicSharedMemorySize, SMEM_TAIL);
    cudaFuncSetAttribute(head_mma_kernel, cudaFuncAttributeMaxDynamicSharedMemorySize, SMEM_HEAD);

    const double lr_gain = sqrt(2.0 / (1.0 + 0.02 * 0.02));
    const float cw_head = (float)(lr_gain / sqrt(27.0));
    const float cb_head = (float)(1.0 / sqrt(3.0));
    const float cw_body = (float)(lr_gain / 24.0);
    const float cb_body = 0.125f;
    const float cw_tail = (float)((5.0 / 3.0) / 24.0);
    const float cb_tail = 0.125f;

    // weight + noise preps
    {
        int N = 5 * 16 * 9 * 64 * 64;
        prep_kernel<<<(N + 255) / 256, 256>>>(body_w, cw_body);
        int M = 16 * 9 * 64 * 8;
        prep_tail_kernel<<<(M + 255) / 256, 256>>>(tail_w, cw_tail);
        int P = 16 * 270 * 270;
        prep_pad_kernel<<<(P + 255) / 256, 256>>>(noise);
        int H = 16 * 80 * 64;
        prep_head_kernel<<<(H + 255) / 256, 256>>>(head_w, cw_head);
    }

    // head (tensorized) -> actA (268)
    {
        dim3 grid(34 * 17, 1, BATCH);
        head_mma_kernel<<<grid, NTHR, SMEM_HEAD>>>(head_b, actA, cb_head);
    }

    // 5 body layers, ping-pong
    __half *src = actA, *dst = actB;
    int Sin = 268;
    for (int l = 0; l < 5; l++) {
        dim3 grid(9, 1, BATCH);
        const __half* wt_l = wt + (size_t)l * 16 * 9 * 4096;
        const float* bias_l = body_b + (size_t)l * 16 * 64;
        body_mma_kernel<<<grid, NTHR, SMEM_BODY>>>(src, wt_l, bias_l, dst, Sin, cb_body);
        __half* t = src; src = dst; dst = t;
        Sin -= 2;
    }

    // tail (tensorized): src 258 -> out 256
    {
        dim3 grid(36, 1, BATCH);
        tail_mma_kernel<<<grid, NTHR, SMEM_TAIL>>>(src, tail_b, out, cb_tail);
    }
}